// round 1
// baseline (speedup 1.0000x reference)
#include <cuda_runtime.h>
#include <math.h>

#define Bsz 512
#define Tsz 512
#define Isz 64
#define Hsz 256

// Scratch: two full-sequence buffers (ping-pong between layers), plus a
// transposed copy of W_hh for the current layer (coalesced access in rec).
__device__ float g_seqA[Bsz * Tsz * Hsz];   // 256 MiB
__device__ float g_seqB[Bsz * Tsz * Hsz];   // 256 MiB
__device__ float g_wt[Hsz * Hsz];           // W_hh^T (k-major)

// ---------------------------------------------------------------------------
// Projection GEMM: C[M, Hsz] = X[M, K] @ W[Hsz, K]^T + b1 + b2
// M = B*T = 262144, K = 64 (layer 0) or 256 (layers 1,2)
// ---------------------------------------------------------------------------
#define PBM 128
#define PBN 64
#define PBK 32
#define PTM 8
#define PTN 4

__global__ __launch_bounds__(256) void proj_kernel(
    const float* __restrict__ X, const float* __restrict__ W,
    const float* __restrict__ b1, const float* __restrict__ b2,
    float* __restrict__ C, int K)
{
    __shared__ float Xs[PBK][PBM + 4];
    __shared__ float Ws[PBK][PBN + 4];

    const int tid = threadIdx.x;
    const int tx = tid & 15;    // n-direction (16 * PTN = 64)
    const int ty = tid >> 4;    // m-direction (16 * PTM = 128)
    const int m0 = blockIdx.x * PBM;
    const int n0 = blockIdx.y * PBN;

    float acc[PTM][PTN];
#pragma unroll
    for (int i = 0; i < PTM; i++)
#pragma unroll
        for (int j = 0; j < PTN; j++) acc[i][j] = 0.0f;

    for (int kt = 0; kt < K; kt += PBK) {
        // Load X tile: 128 rows x 32 k  (1024 float4, 4 per thread)
#pragma unroll
        for (int l = 0; l < 4; l++) {
            int id  = tid + 256 * l;        // 0..1023
            int row = id >> 3;              // 0..127
            int kq  = (id & 7) * 4;         // 0,4,..,28
            float4 v = *(const float4*)&X[(m0 + row) * K + kt + kq];
            Xs[kq + 0][row] = v.x;
            Xs[kq + 1][row] = v.y;
            Xs[kq + 2][row] = v.z;
            Xs[kq + 3][row] = v.w;
        }
        // Load W tile: 64 rows x 32 k  (512 float4, 2 per thread)
#pragma unroll
        for (int l = 0; l < 2; l++) {
            int id  = tid + 256 * l;        // 0..511
            int row = id >> 3;              // 0..63
            int kq  = (id & 7) * 4;
            float4 v = *(const float4*)&W[(n0 + row) * K + kt + kq];
            Ws[kq + 0][row] = v.x;
            Ws[kq + 1][row] = v.y;
            Ws[kq + 2][row] = v.z;
            Ws[kq + 3][row] = v.w;
        }
        __syncthreads();

#pragma unroll
        for (int k = 0; k < PBK; k++) {
            float a[PTM], w[PTN];
#pragma unroll
            for (int i = 0; i < PTM; i++) a[i] = Xs[k][ty * PTM + i];
#pragma unroll
            for (int j = 0; j < PTN; j++) w[j] = Ws[k][tx * PTN + j];
#pragma unroll
            for (int i = 0; i < PTM; i++)
#pragma unroll
                for (int j = 0; j < PTN; j++)
                    acc[i][j] = fmaf(a[i], w[j], acc[i][j]);
        }
        __syncthreads();
    }

#pragma unroll
    for (int j = 0; j < PTN; j++) {
        int n = n0 + tx * PTN + j;
        float bb = b1[n] + b2[n];
#pragma unroll
        for (int i = 0; i < PTM; i++) {
            C[(m0 + ty * PTM + i) * Hsz + n] = acc[i][j] + bb;
        }
    }
}

// ---------------------------------------------------------------------------
// Transpose W_hh [H, H] -> g_wt (k-major: g_wt[k*H + j] = W[j*H + k])
// ---------------------------------------------------------------------------
__global__ void transpose_kernel(const float* __restrict__ w)
{
    int k = blockIdx.x;
    int j = threadIdx.x;
    g_wt[k * Hsz + j] = w[j * Hsz + k];
}

// ---------------------------------------------------------------------------
// Recurrence (in-place): seq[b,t,:] holds pre_t on input, h_t on output.
// 128 CTAs x 4 batch rows; h kept in smem; W_hh^T streamed from L2.
// ---------------------------------------------------------------------------
#define RM 4   // batch rows per CTA

__global__ __launch_bounds__(256) void rec_kernel(float* __restrict__ seq)
{
    __shared__ __align__(16) float hs[RM][Hsz];
    const int j  = threadIdx.x;            // output hidden index
    const int b0 = blockIdx.x * RM;

#pragma unroll
    for (int m = 0; m < RM; m++) hs[m][j] = 0.0f;
    __syncthreads();

    const float* __restrict__ wt = g_wt;

    for (int t = 0; t < Tsz; t++) {
        // pre-activation for this step (input projection + biases)
        float acc0 = seq[((b0 + 0) * Tsz + t) * Hsz + j];
        float acc1 = seq[((b0 + 1) * Tsz + t) * Hsz + j];
        float acc2 = seq[((b0 + 2) * Tsz + t) * Hsz + j];
        float acc3 = seq[((b0 + 3) * Tsz + t) * Hsz + j];

#pragma unroll 8
        for (int k = 0; k < Hsz; k += 4) {
            float w0 = wt[(k + 0) * Hsz + j];
            float w1 = wt[(k + 1) * Hsz + j];
            float w2 = wt[(k + 2) * Hsz + j];
            float w3 = wt[(k + 3) * Hsz + j];
            float4 h0 = *(const float4*)&hs[0][k];
            float4 h1 = *(const float4*)&hs[1][k];
            float4 h2 = *(const float4*)&hs[2][k];
            float4 h3 = *(const float4*)&hs[3][k];
            acc0 = fmaf(w0, h0.x, acc0); acc0 = fmaf(w1, h0.y, acc0);
            acc0 = fmaf(w2, h0.z, acc0); acc0 = fmaf(w3, h0.w, acc0);
            acc1 = fmaf(w0, h1.x, acc1); acc1 = fmaf(w1, h1.y, acc1);
            acc1 = fmaf(w2, h1.z, acc1); acc1 = fmaf(w3, h1.w, acc1);
            acc2 = fmaf(w0, h2.x, acc2); acc2 = fmaf(w1, h2.y, acc2);
            acc2 = fmaf(w2, h2.z, acc2); acc2 = fmaf(w3, h2.w, acc2);
            acc3 = fmaf(w0, h3.x, acc3); acc3 = fmaf(w1, h3.y, acc3);
            acc3 = fmaf(w2, h3.z, acc3); acc3 = fmaf(w3, h3.w, acc3);
        }

        acc0 = tanhf(acc0);
        acc1 = tanhf(acc1);
        acc2 = tanhf(acc2);
        acc3 = tanhf(acc3);

        __syncthreads();   // everyone done reading old h
        hs[0][j] = acc0;
        hs[1][j] = acc1;
        hs[2][j] = acc2;
        hs[3][j] = acc3;
        seq[((b0 + 0) * Tsz + t) * Hsz + j] = acc0;
        seq[((b0 + 1) * Tsz + t) * Hsz + j] = acc1;
        seq[((b0 + 2) * Tsz + t) * Hsz + j] = acc2;
        seq[((b0 + 3) * Tsz + t) * Hsz + j] = acc3;
        __syncthreads();   // new h visible before next step
    }
}

// ---------------------------------------------------------------------------
// Final FC: out[b] = h[b, T-1, :] . w_fc + b_fc     (one warp per batch row)
// ---------------------------------------------------------------------------
__global__ __launch_bounds__(256) void fc_kernel(
    const float* __restrict__ seq, const float* __restrict__ wfc,
    const float* __restrict__ bfc, float* __restrict__ out)
{
    int warp = (blockIdx.x * blockDim.x + threadIdx.x) >> 5;
    int lane = threadIdx.x & 31;
    if (warp >= Bsz) return;
    const float* hrow = &seq[(warp * Tsz + (Tsz - 1)) * Hsz];
    float s = 0.0f;
#pragma unroll
    for (int i = lane; i < Hsz; i += 32) s = fmaf(hrow[i], wfc[i], s);
#pragma unroll
    for (int o = 16; o; o >>= 1) s += __shfl_xor_sync(0xffffffffu, s, o);
    if (lane == 0) out[warp] = s + bfc[0];
}

// ---------------------------------------------------------------------------
extern "C" void kernel_launch(void* const* d_in, const int* in_sizes, int n_in,
                              void* d_out, int out_size)
{
    const float* x     = (const float*)d_in[0];
    const float* w_ih0 = (const float*)d_in[1];
    const float* w_hh0 = (const float*)d_in[2];
    const float* b_ih0 = (const float*)d_in[3];
    const float* b_hh0 = (const float*)d_in[4];
    const float* w_ih1 = (const float*)d_in[5];
    const float* w_hh1 = (const float*)d_in[6];
    const float* b_ih1 = (const float*)d_in[7];
    const float* b_hh1 = (const float*)d_in[8];
    const float* w_ih2 = (const float*)d_in[9];
    const float* w_hh2 = (const float*)d_in[10];
    const float* b_ih2 = (const float*)d_in[11];
    const float* b_hh2 = (const float*)d_in[12];
    const float* w_fc  = (const float*)d_in[13];
    const float* b_fc  = (const float*)d_in[14];
    float* out = (float*)d_out;

    float *seqA, *seqB;
    cudaGetSymbolAddress((void**)&seqA, g_seqA);
    cudaGetSymbolAddress((void**)&seqB, g_seqB);

    dim3 pgrid(Bsz * Tsz / PBM, Hsz / PBN);   // (2048, 4)

    // Layer 0
    proj_kernel<<<pgrid, 256>>>(x, w_ih0, b_ih0, b_hh0, seqA, Isz);
    transpose_kernel<<<Hsz, Hsz>>>(w_hh0);
    rec_kernel<<<Bsz / RM, Hsz>>>(seqA);

    // Layer 1
    proj_kernel<<<pgrid, 256>>>(seqA, w_ih1, b_ih1, b_hh1, seqB, Hsz);
    transpose_kernel<<<Hsz, Hsz>>>(w_hh1);
    rec_kernel<<<Bsz / RM, Hsz>>>(seqB);

    // Layer 2
    proj_kernel<<<pgrid, 256>>>(seqB, w_ih2, b_ih2, b_hh2, seqA, Hsz);
    transpose_kernel<<<Hsz, Hsz>>>(w_hh2);
    rec_kernel<<<Bsz / RM, Hsz>>>(seqA);

    // Head
    fc_kernel<<<(Bsz * 32 + 255) / 256, 256>>>(seqA, w_fc, b_fc, out);
}

// round 2
// speedup vs baseline: 1.5404x; 1.5404x over previous
#include <cuda_runtime.h>
#include <math.h>
#include <stdint.h>

#define Bsz 512
#define Tsz 512
#define Isz 64
#define Hsz 256

// Scratch: two full-sequence buffers (ping-pong between layers).
__device__ float g_seqA[Bsz * Tsz * Hsz];   // 256 MiB
__device__ float g_seqB[Bsz * Tsz * Hsz];   // 256 MiB

__device__ __forceinline__ uint32_t smem_u32(const void* p) {
    uint32_t a;
    asm("{ .reg .u64 t; cvta.to.shared.u64 t, %1; cvt.u32.u64 %0, t; }"
        : "=r"(a) : "l"(p));
    return a;
}

// ---------------------------------------------------------------------------
// Projection GEMM: C[M, Hsz] = X[M, K] @ W[Hsz, K]^T + b1 + b2
// M = B*T = 262144, K = 64 (layer 0) or 256 (layers 1,2)
// ---------------------------------------------------------------------------
#define PBM 128
#define PBN 64
#define PBK 32
#define PTM 8
#define PTN 4

__global__ __launch_bounds__(256) void proj_kernel(
    const float* __restrict__ X, const float* __restrict__ W,
    const float* __restrict__ b1, const float* __restrict__ b2,
    float* __restrict__ C, int K)
{
    __shared__ float Xs[PBK][PBM + 4];
    __shared__ float Ws[PBK][PBN + 4];

    const int tid = threadIdx.x;
    const int tx = tid & 15;    // n-direction (16 * PTN = 64)
    const int ty = tid >> 4;    // m-direction (16 * PTM = 128)
    const int m0 = blockIdx.x * PBM;
    const int n0 = blockIdx.y * PBN;

    float acc[PTM][PTN];
#pragma unroll
    for (int i = 0; i < PTM; i++)
#pragma unroll
        for (int j = 0; j < PTN; j++) acc[i][j] = 0.0f;

    for (int kt = 0; kt < K; kt += PBK) {
#pragma unroll
        for (int l = 0; l < 4; l++) {
            int id  = tid + 256 * l;
            int row = id >> 3;
            int kq  = (id & 7) * 4;
            float4 v = *(const float4*)&X[(m0 + row) * K + kt + kq];
            Xs[kq + 0][row] = v.x;
            Xs[kq + 1][row] = v.y;
            Xs[kq + 2][row] = v.z;
            Xs[kq + 3][row] = v.w;
        }
#pragma unroll
        for (int l = 0; l < 2; l++) {
            int id  = tid + 256 * l;
            int row = id >> 3;
            int kq  = (id & 7) * 4;
            float4 v = *(const float4*)&W[(n0 + row) * K + kt + kq];
            Ws[kq + 0][row] = v.x;
            Ws[kq + 1][row] = v.y;
            Ws[kq + 2][row] = v.z;
            Ws[kq + 3][row] = v.w;
        }
        __syncthreads();

#pragma unroll
        for (int k = 0; k < PBK; k++) {
            float a[PTM], w[PTN];
#pragma unroll
            for (int i = 0; i < PTM; i++) a[i] = Xs[k][ty * PTM + i];
#pragma unroll
            for (int j = 0; j < PTN; j++) w[j] = Ws[k][tx * PTN + j];
#pragma unroll
            for (int i = 0; i < PTM; i++)
#pragma unroll
                for (int j = 0; j < PTN; j++)
                    acc[i][j] = fmaf(a[i], w[j], acc[i][j]);
        }
        __syncthreads();
    }

#pragma unroll
    for (int j = 0; j < PTN; j++) {
        int n = n0 + tx * PTN + j;
        float bb = b1[n] + b2[n];
#pragma unroll
        for (int i = 0; i < PTM; i++) {
            C[(m0 + ty * PTM + i) * Hsz + n] = acc[i][j] + bb;
        }
    }
}

// ---------------------------------------------------------------------------
// Recurrence with W_hh resident in SMEM, hidden dim split across a 2-CTA
// cluster. Each cluster owns RMC batch rows; each CTA computes its 128-j
// half of h_t and exchanges via DSMEM. In-place on seq (pre -> h).
// ---------------------------------------------------------------------------
#define RMC     8           // batch rows per cluster
#define WPITCH  260         // floats per W row in smem (260 % 32 == 4, float4 ok)
#define REC_SMEM ((128 * WPITCH + 2 * RMC * Hsz) * 4)   // 149504 bytes

__global__ void __launch_bounds__(256) __cluster_dims__(2, 1, 1)
rec2_kernel(const float* __restrict__ w_hh, float* __restrict__ seq)
{
    extern __shared__ float sm[];
    float* Wsm   = sm;                          // [128][WPITCH], j-major
    float* hbuf0 = sm + 128 * WPITCH;           // [RMC][256]  (global j index)
    float* hbuf1 = hbuf0 + RMC * Hsz;

    const int tid  = threadIdx.x;
    const unsigned rank = blockIdx.x & 1;       // == cluster_ctarank
    const int jl   = tid & 127;                 // local j
    const int jg   = (int)rank * 128 + jl;      // global j
    const int r0   = (tid >> 7) * 4;            // this thread's 4 batch rows
    const int b0   = (blockIdx.x >> 1) * RMC;   // cluster's batch base

    // Load this CTA's half of W_hh, j-major (coalesced gmem, conflict-free smem)
    for (int idx = tid; idx < 128 * Hsz; idx += 256) {
        int j = idx >> 8, k = idx & 255;
        Wsm[j * WPITCH + k] = w_hh[((int)rank * 128 + j) * Hsz + k];
    }
    for (int idx = tid; idx < RMC * Hsz; idx += 256) hbuf0[idx] = 0.0f;

    // Peer-CTA addresses of the two h buffers
    uint32_t l0 = smem_u32(hbuf0), l1 = smem_u32(hbuf1);
    uint32_t p0, p1;
    asm("mapa.shared::cluster.u32 %0, %1, %2;" : "=r"(p0) : "r"(l0), "r"(rank ^ 1u));
    asm("mapa.shared::cluster.u32 %0, %1, %2;" : "=r"(p1) : "r"(l1), "r"(rank ^ 1u));

    asm volatile("barrier.cluster.arrive.aligned;" ::: "memory");
    asm volatile("barrier.cluster.wait.aligned;" ::: "memory");

    const float* wrow = Wsm + jl * WPITCH;

    // Prefetch pre-activations for t = 0
    float n0 = seq[((b0 + r0 + 0) * Tsz + 0) * Hsz + jg];
    float n1 = seq[((b0 + r0 + 1) * Tsz + 0) * Hsz + jg];
    float n2 = seq[((b0 + r0 + 2) * Tsz + 0) * Hsz + jg];
    float n3 = seq[((b0 + r0 + 3) * Tsz + 0) * Hsz + jg];

    for (int t = 0; t < Tsz; t++) {
        const float* hc = (t & 1) ? hbuf1 : hbuf0;   // read buffer
        float*       hn = (t & 1) ? hbuf0 : hbuf1;   // write buffer
        uint32_t     pn = (t & 1) ? p0   : p1;       // peer write buffer

        float a0 = n0, a1 = n1, a2 = n2, a3 = n3;

        // Prefetch next step's pre-activations (hidden behind the k-loop)
        if (t + 1 < Tsz) {
            n0 = seq[((b0 + r0 + 0) * Tsz + t + 1) * Hsz + jg];
            n1 = seq[((b0 + r0 + 1) * Tsz + t + 1) * Hsz + jg];
            n2 = seq[((b0 + r0 + 2) * Tsz + t + 1) * Hsz + jg];
            n3 = seq[((b0 + r0 + 3) * Tsz + t + 1) * Hsz + jg];
        }

        const float* h0p = hc + (r0 + 0) * Hsz;
        const float* h1p = hc + (r0 + 1) * Hsz;
        const float* h2p = hc + (r0 + 2) * Hsz;
        const float* h3p = hc + (r0 + 3) * Hsz;

#pragma unroll 8
        for (int k = 0; k < Hsz; k += 4) {
            float4 w  = *(const float4*)(wrow + k);
            float4 x0 = *(const float4*)(h0p + k);
            float4 x1 = *(const float4*)(h1p + k);
            float4 x2 = *(const float4*)(h2p + k);
            float4 x3 = *(const float4*)(h3p + k);
            a0 = fmaf(w.x, x0.x, a0); a0 = fmaf(w.y, x0.y, a0);
            a0 = fmaf(w.z, x0.z, a0); a0 = fmaf(w.w, x0.w, a0);
            a1 = fmaf(w.x, x1.x, a1); a1 = fmaf(w.y, x1.y, a1);
            a1 = fmaf(w.z, x1.z, a1); a1 = fmaf(w.w, x1.w, a1);
            a2 = fmaf(w.x, x2.x, a2); a2 = fmaf(w.y, x2.y, a2);
            a2 = fmaf(w.z, x2.z, a2); a2 = fmaf(w.w, x2.w, a2);
            a3 = fmaf(w.x, x3.x, a3); a3 = fmaf(w.y, x3.y, a3);
            a3 = fmaf(w.z, x3.z, a3); a3 = fmaf(w.w, x3.w, a3);
        }

        a0 = tanhf(a0); a1 = tanhf(a1); a2 = tanhf(a2); a3 = tanhf(a3);

        // Publish new h: local smem + peer smem (DSMEM) + gmem sequence
        hn[(r0 + 0) * Hsz + jg] = a0;
        hn[(r0 + 1) * Hsz + jg] = a1;
        hn[(r0 + 2) * Hsz + jg] = a2;
        hn[(r0 + 3) * Hsz + jg] = a3;
        asm volatile("st.shared::cluster.f32 [%0], %1;"
                     :: "r"(pn + ((r0 + 0) * Hsz + jg) * 4), "f"(a0) : "memory");
        asm volatile("st.shared::cluster.f32 [%0], %1;"
                     :: "r"(pn + ((r0 + 1) * Hsz + jg) * 4), "f"(a1) : "memory");
        asm volatile("st.shared::cluster.f32 [%0], %1;"
                     :: "r"(pn + ((r0 + 2) * Hsz + jg) * 4), "f"(a2) : "memory");
        asm volatile("st.shared::cluster.f32 [%0], %1;"
                     :: "r"(pn + ((r0 + 3) * Hsz + jg) * 4), "f"(a3) : "memory");

        seq[((b0 + r0 + 0) * Tsz + t) * Hsz + jg] = a0;
        seq[((b0 + r0 + 1) * Tsz + t) * Hsz + jg] = a1;
        seq[((b0 + r0 + 2) * Tsz + t) * Hsz + jg] = a2;
        seq[((b0 + r0 + 3) * Tsz + t) * Hsz + jg] = a3;

        // One cluster barrier per step: orders this step's h-writes before the
        // peer's next-step reads, and protects the buffer we overwrite next.
        asm volatile("barrier.cluster.arrive.aligned;" ::: "memory");
        asm volatile("barrier.cluster.wait.aligned;" ::: "memory");
    }
}

// ---------------------------------------------------------------------------
// Final FC: out[b] = h[b, T-1, :] . w_fc + b_fc     (one warp per batch row)
// ---------------------------------------------------------------------------
__global__ __launch_bounds__(256) void fc_kernel(
    const float* __restrict__ seq, const float* __restrict__ wfc,
    const float* __restrict__ bfc, float* __restrict__ out)
{
    int warp = (blockIdx.x * blockDim.x + threadIdx.x) >> 5;
    int lane = threadIdx.x & 31;
    if (warp >= Bsz) return;
    const float* hrow = &seq[(warp * Tsz + (Tsz - 1)) * Hsz];
    float s = 0.0f;
#pragma unroll
    for (int i = lane; i < Hsz; i += 32) s = fmaf(hrow[i], wfc[i], s);
#pragma unroll
    for (int o = 16; o; o >>= 1) s += __shfl_xor_sync(0xffffffffu, s, o);
    if (lane == 0) out[warp] = s + bfc[0];
}

// ---------------------------------------------------------------------------
extern "C" void kernel_launch(void* const* d_in, const int* in_sizes, int n_in,
                              void* d_out, int out_size)
{
    const float* x     = (const float*)d_in[0];
    const float* w_ih0 = (const float*)d_in[1];
    const float* w_hh0 = (const float*)d_in[2];
    const float* b_ih0 = (const float*)d_in[3];
    const float* b_hh0 = (const float*)d_in[4];
    const float* w_ih1 = (const float*)d_in[5];
    const float* w_hh1 = (const float*)d_in[6];
    const float* b_ih1 = (const float*)d_in[7];
    const float* b_hh1 = (const float*)d_in[8];
    const float* w_ih2 = (const float*)d_in[9];
    const float* w_hh2 = (const float*)d_in[10];
    const float* b_ih2 = (const float*)d_in[11];
    const float* b_hh2 = (const float*)d_in[12];
    const float* w_fc  = (const float*)d_in[13];
    const float* b_fc  = (const float*)d_in[14];
    float* out = (float*)d_out;

    float *seqA, *seqB;
    cudaGetSymbolAddress((void**)&seqA, g_seqA);
    cudaGetSymbolAddress((void**)&seqB, g_seqB);

    cudaFuncSetAttribute(rec2_kernel,
                         cudaFuncAttributeMaxDynamicSharedMemorySize, REC_SMEM);

    dim3 pgrid(Bsz * Tsz / PBM, Hsz / PBN);   // (2048, 4)
    const int rec_grid = (Bsz / RMC) * 2;     // 128 CTAs = 64 clusters

    // Layer 0
    proj_kernel<<<pgrid, 256>>>(x, w_ih0, b_ih0, b_hh0, seqA, Isz);
    rec2_kernel<<<rec_grid, 256, REC_SMEM>>>(w_hh0, seqA);

    // Layer 1
    proj_kernel<<<pgrid, 256>>>(seqA, w_ih1, b_ih1, b_hh1, seqB, Hsz);
    rec2_kernel<<<rec_grid, 256, REC_SMEM>>>(w_hh1, seqB);

    // Layer 2
    proj_kernel<<<pgrid, 256>>>(seqB, w_ih2, b_ih2, b_hh2, seqA, Hsz);
    rec2_kernel<<<rec_grid, 256, REC_SMEM>>>(w_hh2, seqA);

    // Head
    fc_kernel<<<(Bsz * 32 + 255) / 256, 256>>>(seqA, w_fc, b_fc, out);
}